// round 3
// baseline (speedup 1.0000x reference)
#include <cuda_runtime.h>
#include <math.h>

#define BB 8
#define NN 2048
#define IND 128
#define OUTD 64
#define NEG_SLOPE 0.2f
#define NCHUNK 16
#define CHUNK 128

// ---------------- scratch (static device globals; no allocations) ----------------
__device__ float g_hp[BB * NN * OUTD];        // projected features (4 MB)
__device__ float g_s[BB * NN];                // s_i = hp . a_src
__device__ float g_d[BB * NN];                // d_j = hp . a_dst
__device__ float g_sortedD[BB * NN];          // per-batch ascending d
__device__ int   g_sortIdx[BB * NN];
__device__ float g_wp[BB * NN];               // exp(d) at sorted position
__device__ float g_wq[BB * NN];               // exp(0.2 d) at sorted position
__device__ float g_ctot[BB * NCHUNK * 130];   // per-chunk totals [b][c][series]
__device__ float g_tab[(size_t)BB * 2049 * 130]; // [b][k][0..64]=sufPos, [65..129]=prefNeg

// ---------------- kernel 1: hp = h @ W_fc + b_fc, fused s/d epilogue ----------------
// 64 rows x 64 cols per block; 256 threads = 16 col-quads x 16 row-groups(4 rows).
__global__ void projectK(const float* __restrict__ h, const float* __restrict__ W,
                         const float* __restrict__ bfc,
                         const float* __restrict__ asrc, const float* __restrict__ adst) {
    extern __shared__ float sm[];
    float* sH = sm;                 // [64][128]
    float* sW = sm + 64 * IND;      // [128][64]
    const int t = threadIdx.x;
    const int rowBase = blockIdx.x * 64;

    const float4* hsrc = (const float4*)(h + (size_t)rowBase * IND);
    float4* sH4 = (float4*)sH;
#pragma unroll
    for (int i = t; i < 64 * IND / 4; i += 256) sH4[i] = hsrc[i];
    const float4* wsrc = (const float4*)W;
    float4* sW4 = (float4*)sW;
#pragma unroll
    for (int i = t; i < IND * OUTD / 4; i += 256) sW4[i] = wsrc[i];
    __syncthreads();

    const int q = t & 15;     // col quad: cols 4q..4q+3
    const int g = t >> 4;     // row group: rows 4g..4g+3
    const int c0 = q * 4;
    const int r0 = g * 4;

    const float4 b4 = *(const float4*)(bfc + c0);
    float acc[4][4];
#pragma unroll
    for (int r = 0; r < 4; r++) {
        acc[r][0] = b4.x; acc[r][1] = b4.y; acc[r][2] = b4.z; acc[r][3] = b4.w;
    }

    for (int k = 0; k < IND; k += 4) {
        float hv[4][4], wv[4][4];
#pragma unroll
        for (int r = 0; r < 4; r++) {
            const float4 a = *(const float4*)&sH[(r0 + r) * IND + k];
            hv[r][0] = a.x; hv[r][1] = a.y; hv[r][2] = a.z; hv[r][3] = a.w;
        }
#pragma unroll
        for (int kk = 0; kk < 4; kk++) {
            const float4 w = *(const float4*)&sW[(k + kk) * OUTD + c0];
            wv[kk][0] = w.x; wv[kk][1] = w.y; wv[kk][2] = w.z; wv[kk][3] = w.w;
        }
#pragma unroll
        for (int kk = 0; kk < 4; kk++)
#pragma unroll
            for (int r = 0; r < 4; r++)
#pragma unroll
                for (int c = 0; c < 4; c++)
                    acc[r][c] = fmaf(hv[r][kk], wv[kk][c], acc[r][c]);
    }

    float* outp = g_hp + (size_t)rowBase * OUTD;
#pragma unroll
    for (int r = 0; r < 4; r++) {
        float4 o; o.x = acc[r][0]; o.y = acc[r][1]; o.z = acc[r][2]; o.w = acc[r][3];
        *(float4*)&outp[(size_t)(r0 + r) * OUTD + c0] = o;
    }

    // ---- fused s/d epilogue: half-warp (16-thread) reduction over the 64 cols ----
    const float4 as4 = *(const float4*)(asrc + c0);
    const float4 ad4 = *(const float4*)(adst + c0);
    float sp[4], dp[4];
#pragma unroll
    for (int r = 0; r < 4; r++) {
        sp[r] = fmaf(acc[r][0], as4.x, fmaf(acc[r][1], as4.y,
                 fmaf(acc[r][2], as4.z, acc[r][3] * as4.w)));
        dp[r] = fmaf(acc[r][0], ad4.x, fmaf(acc[r][1], ad4.y,
                 fmaf(acc[r][2], ad4.z, acc[r][3] * ad4.w)));
    }
#pragma unroll
    for (int o = 1; o < 16; o <<= 1) {
#pragma unroll
        for (int r = 0; r < 4; r++) {
            sp[r] += __shfl_xor_sync(0xffffffffu, sp[r], o);
            dp[r] += __shfl_xor_sync(0xffffffffu, dp[r], o);
        }
    }
    if (q == 0) {
#pragma unroll
        for (int r = 0; r < 4; r++) {
            g_s[rowBase + r0 + r] = sp[r];
            g_d[rowBase + r0 + r] = dp[r];
        }
    }
}

// ---------------- kernel 2: per-batch bitonic sort, packed 64-bit (key|idx) ----------------
__global__ void sortK() {
    const int b = blockIdx.x;
    __shared__ unsigned long long su[NN];
    const int t = threadIdx.x;  // 1024

    for (int i = t; i < NN; i += 1024) {
        const unsigned bits = __float_as_uint(g_d[b * NN + i]);
        const unsigned key = bits ^ ((bits & 0x80000000u) ? 0xFFFFFFFFu : 0x80000000u);
        su[i] = ((unsigned long long)key << 32) | (unsigned)i;
    }
    __syncthreads();

    for (int k = 2; k <= NN; k <<= 1) {
        for (int j = k >> 1; j > 0; j >>= 1) {
            const int i = ((t & ~(j - 1)) << 1) | (t & (j - 1));
            const int partner = i | j;
            const bool up = ((i & k) == 0);
            const unsigned long long A = su[i], B = su[partner];
            const unsigned long long lo_ = (A < B) ? A : B;
            const unsigned long long hi_ = (A < B) ? B : A;
            su[i] = up ? lo_ : hi_;
            su[partner] = up ? hi_ : lo_;
            if (j >= 64) __syncthreads(); else __syncwarp();
        }
        __syncthreads();
    }

    for (int i = t; i < NN; i += 1024) {
        const unsigned long long u = su[i];
        const unsigned key = (unsigned)(u >> 32);
        const unsigned bits = key ^ ((key & 0x80000000u) ? 0x80000000u : 0xFFFFFFFFu);
        const float dv = __uint_as_float(bits);
        g_sortedD[b * NN + i] = dv;
        g_sortIdx[b * NN + i] = (int)(u & 0xFFFFFFFFu);
        g_wp[b * NN + i] = __expf(dv);
        g_wq[b * NN + i] = __expf(NEG_SLOPE * dv);
    }
}

// ---------------- shared gather for the scan kernels ----------------
// sVal[pos][0..63] = hp row at sorted position pos (float4 coalesced), sVal[pos][64] = 1.
__device__ __forceinline__ void gatherChunk(int b, int c, float* sVal,
                                            float* swp, float* swq, int* sj) {
    const int t = threadIdx.x;
    const int base = b * NN + c * CHUNK;
    if (t < CHUNK) {
        sj[t] = g_sortIdx[base + t];
        swp[t] = g_wp[base + t];
        swq[t] = g_wq[base + t];
        sVal[t * 68 + 64] = 1.0f;
    }
    __syncthreads();
#pragma unroll
    for (int f = t; f < CHUNK * 16; f += 256) {
        const int row = f >> 4, quad = f & 15;
        const int j = sj[row];
        const float4 v = *(const float4*)(g_hp + ((size_t)b * NN + j) * OUTD + quad * 4);
        *(float4*)&sVal[row * 68 + quad * 4] = v;
    }
    __syncthreads();
}

// ---------------- kernel 3a: per-chunk totals ----------------
__global__ void scanA() {
    const int c = blockIdx.x, b = blockIdx.y;
    __shared__ float sVal[CHUNK * 68];
    __shared__ float swp[CHUNK], swq[CHUNK];
    __shared__ int sj[CHUNK];
    gatherChunk(b, c, sVal, swp, swq, sj);

    const int t = threadIdx.x;
    if (t < 130) {
        const int dim = (t < 65) ? t : t - 65;
        const float* w = (t < 65) ? swp : swq;
        float acc = 0.f;
#pragma unroll 4
        for (int pos = 0; pos < CHUNK; pos++)
            acc = fmaf(w[pos], sVal[pos * 68 + dim], acc);
        g_ctot[(b * NCHUNK + c) * 130 + t] = acc;
    }
}

// ---------------- kernel 3b: offsets + local scan -> final g_tab ----------------
__global__ void scanC() {
    const int c = blockIdx.x, b = blockIdx.y;
    __shared__ float sVal[CHUNK * 68];
    __shared__ float swp[CHUNK], swq[CHUNK];
    __shared__ int sj[CHUNK];
    gatherChunk(b, c, sVal, swp, swq, sj);

    const int t = threadIdx.x;
    if (t < 130) {
        float* tabb = g_tab + (size_t)b * 2049 * 130;
        const int k0 = c * CHUNK;
        if (t < 65) {
            // positive branch: suffix sums; offset = totals of chunks after c
            float acc = 0.f;
            for (int cc = c + 1; cc < NCHUNK; cc++)
                acc += g_ctot[(b * NCHUNK + cc) * 130 + t];
#pragma unroll 4
            for (int pos = CHUNK - 1; pos >= 0; pos--) {
                acc = fmaf(swp[pos], sVal[pos * 68 + t], acc);
                tabb[(size_t)(k0 + pos) * 130 + t] = acc;     // sufPos[k0+pos]
            }
            if (c == NCHUNK - 1) tabb[(size_t)2048 * 130 + t] = 0.f;  // sufPos[2048]
        } else {
            // negative branch: prefix sums; offset = totals of chunks before c
            const int dim = t - 65;
            float acc = 0.f;
            for (int cc = 0; cc < c; cc++)
                acc += g_ctot[(b * NCHUNK + cc) * 130 + t];
#pragma unroll 4
            for (int pos = 0; pos < CHUNK; pos++) {
                acc = fmaf(swq[pos], sVal[pos * 68 + dim], acc);
                tabb[(size_t)(k0 + pos + 1) * 130 + 65 + dim] = acc;  // prefNeg[k0+pos+1]
            }
            if (c == 0) tabb[65 + dim] = 0.f;                 // prefNeg[0]
        }
    }
}

// ---------------- kernel 4: per-row output (256 rows/block) ----------------
__global__ void outK(const float* __restrict__ battn, float* __restrict__ out) {
    __shared__ float sd[NN];
    __shared__ float ssi[256];
    __shared__ int slo[256];
    const int b = blockIdx.x >> 3;                 // 8 blocks per batch
    const int rb = (blockIdx.x & 7) * 256;         // row base within batch
    const int t = threadIdx.x;

    const float4* src = (const float4*)(g_sortedD + b * NN);
    float4* dst = (float4*)sd;
    for (int i = t; i < NN / 4; i += 256) dst[i] = src[i];
    __syncthreads();

    // phase 1: one row per thread — binary search for threshold
    const float si = g_s[b * NN + rb + t] + *battn;
    const float tt = -si;                          // d_j >= tt -> positive branch
    int lo = 0, hi = NN;
    while (lo < hi) {
        const int mid = (lo + hi) >> 1;
        if (sd[mid] < tt) lo = mid + 1; else hi = mid;
    }
    ssi[t] = si; slo[t] = lo;
    __syncthreads();

    // phase 2: warp per row, 32 rows per warp
    const int warp = t >> 5, lane = t & 31;
#pragma unroll 2
    for (int rr = 0; rr < 32; rr++) {
        const int lr = warp * 32 + rr;
        const int row = b * NN + rb + lr;
        const float s2 = ssi[lr];
        const float P = __expf(s2);
        const float Q = __expf(NEG_SLOPE * s2);
        const float* tb = g_tab + ((size_t)b * 2049 + slo[lr]) * 130;
        const float den = fmaf(P, tb[64], Q * tb[129]);
        const float inv = 1.0f / den;
        float* orow = out + (size_t)row * OUTD;
#pragma unroll
        for (int d0 = 0; d0 < 2; d0++) {
            const int d = lane + d0 * 32;
            const float num = fmaf(P, tb[d], Q * tb[65 + d]);
            const float o = num * inv;
            orow[d] = (o > 0.f) ? o : (__expf(o) - 1.0f);   // ELU (alpha=1)
        }
    }
}

// ---------------- launch ----------------
extern "C" void kernel_launch(void* const* d_in, const int* in_sizes, int n_in,
                              void* d_out, int out_size) {
    const float* h     = (const float*)d_in[0];
    const float* W     = (const float*)d_in[1];
    const float* bfc   = (const float*)d_in[2];
    const float* asrc  = (const float*)d_in[3];
    const float* adst  = (const float*)d_in[4];
    const float* battn = (const float*)d_in[5];
    float* out = (float*)d_out;

    cudaFuncSetAttribute(projectK, cudaFuncAttributeMaxDynamicSharedMemorySize, 64 * 1024);

    projectK<<<(BB * NN) / 64, 256, 64 * 1024>>>(h, W, bfc, asrc, adst);
    sortK<<<BB, 1024>>>();
    dim3 sg(NCHUNK, BB);
    scanA<<<sg, 256>>>();
    scanC<<<sg, 256>>>();
    outK<<<(BB * NN) / 256, 256>>>(battn, out);
}